// round 16
// baseline (speedup 1.0000x reference)
#include <cuda_runtime.h>
#include <cstdint>
#include <cfloat>

// Problem constants
#define BB 32
#define KK 5
#define TT 12
#define VV 50257
#define HH 512
#define NBEAMS (BB*KK)           // 160
#define NPART 32                 // v-partitions per batch row
#define PERV ((VV + NPART - 1) / NPART)   // 1571 -> ng in [391,393]
#define NTOPK (NPART*BB)         // 1024 topk blocks

// Output layout: ONE f32 buffer, outputs cast to f32, concatenated in
// reference return order (element offsets). Verified: rel_err == 0.
#define OFF_SEQ   ((size_t)0)                         // 32*5*13 = 2080
#define OFF_BSLP  ((size_t)2080)
#define OFF_SUM   (OFF_BSLP + (size_t)BB*KK*13*VV)    // 104536640
#define OFF_STATE (OFF_SUM + (size_t)NBEAMS)          // 104536800 (mod 4 == 0)

#define NROWS_BSLP (BB*KK*(TT+1))   // 2080
#define XBLK 13                      // x-blocks per bslp row (13*1024 >= 12564)
#define NBSLP_BLKS (NROWS_BSLP*XBLK) // 27040
#define NSTATE_BLKS (2*NBEAMS)       // 320
#define NGATHER_PER_B (KK*(TT+1)*XBLK + 2*KK)   // 845 + 10 = 855

// Scratch (static device globals; no allocation)
__device__ float g_part_val[BB * NPART * 5];
__device__ int   g_part_idx[BB * NPART * 5];
__device__ int   g_beam_ix[NBEAMS];
__device__ unsigned int g_done[BB];    // zero-init; reset after each use
__device__ unsigned int g_ready[BB];   // per-row publish flag
__device__ unsigned int g_gcnt[BB];    // per-row gather-completion counter

__device__ __forceinline__ bool better(float va, int ia, float vb, int ib) {
    return (va > vb) || (va == vb && ia < ib);
}

__device__ __forceinline__ void insert5(float val, int idx, float tv[5], int ti[5]) {
    if (better(val, idx, tv[4], ti[4])) {
        tv[4] = val; ti[4] = idx;
#pragma unroll
        for (int j = 4; j > 0; j--) {
            if (better(tv[j], ti[j], tv[j-1], ti[j-1])) {
                float fv = tv[j]; tv[j] = tv[j-1]; tv[j-1] = fv;
                int   iv = ti[j]; ti[j] = ti[j-1]; ti[j-1] = iv;
            }
        }
    }
}

__device__ __forceinline__ unsigned fkey(float f) {
    unsigned u = __float_as_uint(f);
    return (u & 0x80000000u) ? ~u : (u | 0x80000000u);
}

__device__ __forceinline__ float4 ldg128_nocse(const float* p) {
    float4 v;
    asm volatile("ld.global.nc.v4.f32 {%0,%1,%2,%3}, [%4];"
                 : "=f"(v.x), "=f"(v.y), "=f"(v.z), "=f"(v.w) : "l"(p));
    return v;
}

#define WARP_ARGMAX(bv, bi) \
    { _Pragma("unroll") \
      for (int s_ = 16; s_ > 0; s_ >>= 1) { \
          float ov = __shfl_xor_sync(0xFFFFFFFF, bv, s_); \
          int   oi = __shfl_xor_sync(0xFFFFFFFF, bi, s_); \
          if (better(ov, oi, bv, bi)) { bv = ov; bi = oi; } \
      } }

// ---------------------------------------------------------------------------
// Topk block body (R15 logic). Last block per row publishes g_ready[b].
// ---------------------------------------------------------------------------
__device__ void topk_block(
    int b, int part,
    const float* __restrict__ logprobs,
    const float* __restrict__ bsum,
    const int*   __restrict__ beam_seq,
    float* __restrict__ out)
{
    const int tid     = threadIdx.x;
    const int lane    = tid & 31;
    const int wid     = tid >> 5;
    const int v_start = part * PERV;
    const int v_end   = min(v_start + PERV, VV);
    const int rowbase = b * KK * VV;

    float bs[KK];
#pragma unroll
    for (int k = 0; k < KK; k++) bs[k] = bsum[b * KK + k];

    int s_k[KK], ng[KK];
#pragma unroll
    for (int k = 0; k < KK; k++) {
        int a0 = rowbase + k * VV + v_start;
        int a1 = rowbase + k * VV + v_end;
        int s  = (a0 + 3) & ~3;
        s_k[k] = s;
        ng[k]  = ((a1 & ~3) - s) >> 2;   // >= 1 always
    }

    const int ga = tid, gb = tid + 256;
    float gva[KK], gvb[KK];
    {
        float4 t0 = *reinterpret_cast<const float4*>(logprobs + s_k[0] + 4 * min(ga, ng[0]-1));
        float4 t1 = *reinterpret_cast<const float4*>(logprobs + s_k[1] + 4 * min(ga, ng[1]-1));
        float4 t2 = *reinterpret_cast<const float4*>(logprobs + s_k[2] + 4 * min(ga, ng[2]-1));
        float4 t3 = *reinterpret_cast<const float4*>(logprobs + s_k[3] + 4 * min(ga, ng[3]-1));
        float4 t4 = *reinterpret_cast<const float4*>(logprobs + s_k[4] + 4 * min(ga, ng[4]-1));
        gva[0] = fmaxf(fmaxf(t0.x, t0.y), fmaxf(t0.z, t0.w));
        gva[1] = fmaxf(fmaxf(t1.x, t1.y), fmaxf(t1.z, t1.w));
        gva[2] = fmaxf(fmaxf(t2.x, t2.y), fmaxf(t2.z, t2.w));
        gva[3] = fmaxf(fmaxf(t3.x, t3.y), fmaxf(t3.z, t3.w));
        gva[4] = fmaxf(fmaxf(t4.x, t4.y), fmaxf(t4.z, t4.w));
    }
    {
        float4 t0 = *reinterpret_cast<const float4*>(logprobs + s_k[0] + 4 * min(gb, ng[0]-1));
        float4 t1 = *reinterpret_cast<const float4*>(logprobs + s_k[1] + 4 * min(gb, ng[1]-1));
        float4 t2 = *reinterpret_cast<const float4*>(logprobs + s_k[2] + 4 * min(gb, ng[2]-1));
        float4 t3 = *reinterpret_cast<const float4*>(logprobs + s_k[3] + 4 * min(gb, ng[3]-1));
        float4 t4 = *reinterpret_cast<const float4*>(logprobs + s_k[4] + 4 * min(gb, ng[4]-1));
        gvb[0] = fmaxf(fmaxf(t0.x, t0.y), fmaxf(t0.z, t0.w));
        gvb[1] = fmaxf(fmaxf(t1.x, t1.y), fmaxf(t1.z, t1.w));
        gvb[2] = fmaxf(fmaxf(t2.x, t2.y), fmaxf(t2.z, t2.w));
        gvb[3] = fmaxf(fmaxf(t3.x, t3.y), fmaxf(t3.z, t3.w));
        gvb[4] = fmaxf(fmaxf(t4.x, t4.y), fmaxf(t4.z, t4.w));
    }

    float tm = -FLT_MAX;
#pragma unroll
    for (int k = 0; k < KK; k++) {
        gva[k] = (ga < ng[k]) ? (bs[k] + gva[k]) : -FLT_MAX;
        gvb[k] = (gb < ng[k]) ? (bs[k] + gvb[k]) : -FLT_MAX;
        tm = fmaxf(tm, fmaxf(gva[k], gvb[k]));
    }

    unsigned curk = fkey(tm), Tk = 0;
#pragma unroll
    for (int r = 0; r < 5; r++) {
        unsigned m = __reduce_max_sync(0xFFFFFFFF, curk);
        Tk = m;
        unsigned ball = __ballot_sync(0xFFFFFFFF, curk == m);
        if (lane == __ffs(ball) - 1) curk = 0u;
    }

    float tv[5]; int ti[5];
#pragma unroll
    for (int j = 0; j < 5; j++) { tv[j] = -FLT_MAX; ti[j] = 0x7FFFFFFF; }

#pragma unroll
    for (int k = 0; k < KK; k++) {
        if (fkey(gva[k]) >= Tk && ga < ng[k]) {
            float4 x = ldg128_nocse(logprobs + s_k[k] + 4 * ga);
            const int base = s_k[k] + 4 * ga - rowbase;
            insert5(bs[k] + x.x, base + 0, tv, ti);
            insert5(bs[k] + x.y, base + 1, tv, ti);
            insert5(bs[k] + x.z, base + 2, tv, ti);
            insert5(bs[k] + x.w, base + 3, tv, ti);
        }
        if (fkey(gvb[k]) >= Tk && gb < ng[k]) {
            float4 x = ldg128_nocse(logprobs + s_k[k] + 4 * gb);
            const int base = s_k[k] + 4 * gb - rowbase;
            insert5(bs[k] + x.x, base + 0, tv, ti);
            insert5(bs[k] + x.y, base + 1, tv, ti);
            insert5(bs[k] + x.z, base + 2, tv, ti);
            insert5(bs[k] + x.w, base + 3, tv, ti);
        }
    }

    if (tid < KK) {
        int k = tid;
        int a0 = rowbase + k * VV + v_start;
        int a1 = rowbase + k * VV + v_end;
        for (int o = a0; o < s_k[k]; o++)
            insert5(bs[k] + logprobs[o], o - rowbase, tv, ti);
        for (int o = s_k[k] + 4 * ng[k]; o < a1; o++)
            insert5(bs[k] + logprobs[o], o - rowbase, tv, ti);
    }

    __shared__ float swv[8 * 5];
    __shared__ int   swi[8 * 5];
    {
        float v0 = tv[0], v1 = tv[1], v2 = tv[2], v3 = tv[3], v4 = tv[4];
        int   i0 = ti[0], i1 = ti[1], i2 = ti[2], i3 = ti[3], i4 = ti[4];
#pragma unroll
        for (int r = 0; r < 5; r++) {
            float bv = v0; int bi = i0;
            WARP_ARGMAX(bv, bi)
            if (i0 == bi) {
                v0 = v1; i0 = i1; v1 = v2; i1 = i2;
                v2 = v3; i2 = i3; v3 = v4; i3 = i4;
                v4 = -FLT_MAX; i4 = 0x7FFFFFFF;
            }
            if (lane == 0) { swv[wid * 5 + r] = bv; swi[wid * 5 + r] = bi; }
        }
    }
    __syncthreads();

    if (wid == 0) {
        float v0 = -FLT_MAX, v1 = -FLT_MAX, v2 = -FLT_MAX, v3 = -FLT_MAX, v4 = -FLT_MAX;
        int   i0 = 0x7FFFFFFF, i1 = 0x7FFFFFFF, i2 = 0x7FFFFFFF, i3 = 0x7FFFFFFF, i4 = 0x7FFFFFFF;
        if (lane < 8) {
            v0 = swv[lane*5+0]; i0 = swi[lane*5+0];
            v1 = swv[lane*5+1]; i1 = swi[lane*5+1];
            v2 = swv[lane*5+2]; i2 = swi[lane*5+2];
            v3 = swv[lane*5+3]; i3 = swi[lane*5+3];
            v4 = swv[lane*5+4]; i4 = swi[lane*5+4];
        }
        const int pbase = (b * NPART + part) * 5;
#pragma unroll
        for (int r = 0; r < 5; r++) {
            float bv = v0; int bi = i0;
            WARP_ARGMAX(bv, bi)
            if (i0 == bi && lane < 8) {
                v0 = v1; i0 = i1; v1 = v2; i1 = i2;
                v2 = v3; i2 = i3; v3 = v4; i3 = i4;
                v4 = -FLT_MAX; i4 = 0x7FFFFFFF;
            }
            if (lane == 0) { g_part_val[pbase + r] = bv; g_part_idx[pbase + r] = bi; }
        }

        unsigned int old = 0;
        if (lane == 0) {
            __threadfence();
            old = atomicAdd(&g_done[b], 1u);
        }
        old = __shfl_sync(0xFFFFFFFF, old, 0);

        if (old == NPART - 1) {
            __threadfence();   // acquire: all partials visible
            const int base = (b * NPART + lane) * 5;
            float u0 = g_part_val[base+0], u1 = g_part_val[base+1], u2 = g_part_val[base+2],
                  u3 = g_part_val[base+3], u4 = g_part_val[base+4];
            int   j0 = g_part_idx[base+0], j1 = g_part_idx[base+1], j2 = g_part_idx[base+2],
                  j3 = g_part_idx[base+3], j4 = g_part_idx[base+4];

            int win_bi[5], win_sel[5];
            float win_v[5];
#pragma unroll
            for (int r = 0; r < 5; r++) {
                float bv = u0; int bi = j0;
                WARP_ARGMAX(bv, bi)
                if (j0 == bi) {
                    u0 = u1; j0 = j1; u1 = u2; j1 = j2;
                    u2 = u3; j2 = j3; u3 = u4; j3 = j4;
                    u4 = -FLT_MAX; j4 = 0x7FFFFFFF;
                }
                win_v[r]   = bv;
                win_bi[r]  = bi / VV;
                win_sel[r] = bi - win_bi[r] * VV;
            }

            if (lane < 5) {
                g_beam_ix[b * KK + lane]     = win_bi[lane];
                out[OFF_SUM + b * KK + lane] = win_v[lane];
            }
            for (int idx = lane; idx < 5 * (TT + 1); idx += 32) {
                int j = idx / (TT + 1);
                int t = idx - j * (TT + 1);
                float val;
                if (t < TT) val = (float)beam_seq[(size_t)(b * KK + win_bi[j]) * TT + t];
                else        val = (float)win_sel[j];
                out[OFF_SEQ + (size_t)(b * KK + j) * (TT + 1) + t] = val;
            }
            __syncwarp();
            if (lane == 0) {
                g_done[b] = 0;            // reset for next graph replay
                __threadfence();
                atomicExch(&g_ready[b], 1u);   // publish row b
            }
        }
    }
}

// ---------------------------------------------------------------------------
// Spin until row b is published; broadcast beam_ix via shared.
// ---------------------------------------------------------------------------
__device__ __forceinline__ int wait_and_get_bi(int b, int bk_or_j) {
    __shared__ int s_bi;
    if (threadIdx.x == 0) {
        while (atomicAdd(&g_ready[b], 0u) == 0u) __nanosleep(64);
        __threadfence();
        s_bi = __ldcg(&g_beam_ix[bk_or_j]);
    }
    __syncthreads();
    return s_bi;
}

__device__ __forceinline__ void gather_done_mark(int b) {
    __syncthreads();
    if (threadIdx.x == 0) {
        unsigned o = atomicAdd(&g_gcnt[b], 1u);
        if (o == NGATHER_PER_B - 1) {      // last gather block for row b
            g_gcnt[b] = 0u;
            atomicExch(&g_ready[b], 0u);   // reset for next graph replay
        }
    }
}

// ---------------------------------------------------------------------------
// Single fused kernel. Blocks [0,1024): topk. Then 27040 bslp-copy blocks,
// then 320 state-copy blocks (R10 dual-aligned-load copy logic, unchanged).
// ---------------------------------------------------------------------------
__global__ __launch_bounds__(256, 6) void fused_kernel(
    const float* __restrict__ logprobs,
    const float* __restrict__ bsum,
    const int*   __restrict__ beam_seq,
    const float* __restrict__ bslp,
    const float* __restrict__ unaug,
    const float* __restrict__ state,
    float* __restrict__ out)
{
    const int gid = blockIdx.x;
    const int tid = threadIdx.x;

    if (gid < NTOPK) {
        topk_block(gid >> 5, gid & 31, logprobs, bsum, beam_seq, out);
        return;
    }

    int g2 = gid - NTOPK;
    if (g2 < NBSLP_BLKS) {
        const int row = g2 / XBLK;
        const int xb  = g2 - row * XBLK;
        const int t   = row % (TT + 1);
        const int bk  = row / (TT + 1);
        const int b   = bk / KK;

        const int bi = wait_and_get_bi(b, bk);

        const float* sbase; size_t soff; long slen;
        if (t < TT) {
            sbase = bslp;
            soff  = ((size_t)(b * KK + bi) * TT + t) * VV;
            slen  = (long)NBEAMS * TT * VV;
        } else {
            sbase = unaug;
            soff  = (size_t)(b * KK + bi) * VV;
            slen  = (long)NBEAMS * VV;
        }

        const size_t dst_off = OFF_BSLP + (size_t)row * VV;
        float* dst = out + dst_off;

        const int lead = (int)((4 - (dst_off & 3)) & 3);
        const int nvec = (VV - lead) >> 2;
        const int tb   = xb * 1024;
        const int nv   = min(1024, nvec - tb);

        if (nv > 0) {
            const int  E0 = lead + 4 * tb;
            const int  ps = (int)((soff + (size_t)E0) & 3);
            const long g0 = (long)(soff + (size_t)E0) - ps;   // 16B-aligned

            if (ps == 0) {
#pragma unroll
                for (int q = 0; q < 4; q++) {
                    const int j = q * 256 + tid;
                    if (j < nv) {
                        const float4 v = *reinterpret_cast<const float4*>(sbase + g0 + 4 * (long)j);
                        *reinterpret_cast<float4*>(dst + lead + 4 * (tb + j)) = v;
                    }
                }
            } else {
#pragma unroll
                for (int q = 0; q < 4; q++) {
                    const int j = q * 256 + tid;
                    if (j < nv) {
                        const long a = g0 + 4 * (long)j;
                        float4 lo, hi;
                        lo = *reinterpret_cast<const float4*>(sbase + a);
                        if (a + 8 <= slen) {
                            hi = *reinterpret_cast<const float4*>(sbase + a + 4);
                        } else {
                            hi.x = (a + 4 < slen) ? sbase[a + 4] : 0.0f;
                            hi.y = (a + 5 < slen) ? sbase[a + 5] : 0.0f;
                            hi.z = (a + 6 < slen) ? sbase[a + 6] : 0.0f;
                            hi.w = 0.0f;
                        }
                        float4 v;
                        if (ps == 1)      v = make_float4(lo.y, lo.z, lo.w, hi.x);
                        else if (ps == 2) v = make_float4(lo.z, lo.w, hi.x, hi.y);
                        else              v = make_float4(lo.w, hi.x, hi.y, hi.z);
                        *reinterpret_cast<float4*>(dst + lead + 4 * (tb + j)) = v;
                    }
                }
            }
        }

        // lead + tail scalars (xb 0 only), direct.
        if (xb == 0 && tid < 8) {
            const int tail_start = lead + 4 * nvec;
            if (tid < 4) {
                int v = tid;
                if (v < lead) dst[v] = sbase[soff + v];
            } else {
                int v = tail_start + (tid - 4);
                if (v < VV) dst[v] = sbase[soff + v];
            }
        }

        gather_done_mark(b);
    } else {
        // ---- state copy: one block per (s, j) row ----
        const int r2 = g2 - NBSLP_BLKS;       // 0..319
        const int s  = r2 / NBEAMS;
        const int j  = r2 - s * NBEAMS;       // b*K + k
        const int b  = j / KK;

        const int bi = wait_and_get_bi(b, j);

        const float4* src = reinterpret_cast<const float4*>(
            state + (size_t)s * NBEAMS * HH + (size_t)((j / KK) * KK + bi) * HH);
        float4* dst = reinterpret_cast<float4*>(
            out + OFF_STATE + (size_t)r2 * HH);
        if (tid < HH / 4)
            dst[tid] = src[tid];

        gather_done_mark(b);
    }
}

// ---------------------------------------------------------------------------
extern "C" void kernel_launch(void* const* d_in, const int* in_sizes, int n_in,
                              void* d_out, int out_size) {
    const float* logprobs = (const float*)d_in[0];       // (160, V)
    const float* unaug    = (const float*)d_in[1];       // (160, V)
    const int*   beam_seq = (const int*)d_in[2];         // (32,5,12) int32
    const float* bslp     = (const float*)d_in[3];       // (32,5,12,V)
    const float* bsum     = (const float*)d_in[4];       // (32,5)
    const float* state    = (const float*)d_in[5];       // (2,160,512)
    // d_in[6] = bdash (=5), hardcoded

    float* out = (float*)d_out;

    const int nblocks = NTOPK + NBSLP_BLKS + NSTATE_BLKS;   // 28384
    fused_kernel<<<nblocks, 256>>>(logprobs, bsum, beam_seq,
                                   bslp, unaug, state, out);
}